// round 4
// baseline (speedup 1.0000x reference)
#include <cuda_runtime.h>
#include <cstdint>
#include <math.h>

#define NB 2
#define NH 16
#define NT 2048
#define ND 1024
#define DH 64

// Scratch (allocation-free): Q,K,V,Z in [B][H][T][Dh] layout, fp32. 16 MB each.
__device__ float g_Q[NB*NH*NT*DH];
__device__ float g_K[NB*NH*NT*DH];
__device__ float g_V[NB*NH*NT*DH];
__device__ float g_Z[NB*NH*NT*DH];

// ---------------------------------------------------------------------------
// JAX threefry2x32 with key (0, 42)  (jax.random.key(42), default PRNG)
// ---------------------------------------------------------------------------
__device__ __forceinline__ void threefry_0_42(unsigned x0, unsigned x1,
                                              unsigned &o0, unsigned &o1)
{
    const unsigned ks0 = 0u;
    const unsigned ks1 = 42u;
    const unsigned ks2 = 0x1BD11BDAu ^ 42u;
    x0 += ks0; x1 += ks1;
#define TF_R(r) do { x0 += x1; x1 = __funnelshift_l(x1, x1, (r)); x1 ^= x0; } while (0)
    TF_R(13); TF_R(15); TF_R(26); TF_R(6);
    x0 += ks1; x1 += ks2 + 1u;
    TF_R(17); TF_R(29); TF_R(16); TF_R(24);
    x0 += ks2; x1 += ks0 + 2u;
    TF_R(13); TF_R(15); TF_R(26); TF_R(6);
    x0 += ks0; x1 += ks1 + 3u;
    TF_R(17); TF_R(29); TF_R(16); TF_R(24);
    x0 += ks1; x1 += ks2 + 4u;
    TF_R(13); TF_R(15); TF_R(26); TF_R(6);
    x0 += ks2; x1 += ks0 + 5u;
#undef TF_R
    o0 = x0; o1 = x1;
}

// bits -> N(0,1)*0.01, replicating jax.random.normal's uniform->erfinv path
__device__ __forceinline__ float noise_from_bits(unsigned bits)
{
    float u = __uint_as_float((bits >> 9) | 0x3f800000u) - 1.0f;   // [0,1)
    const float lo = -0.99999994f;                                 // nextafter(-1,0)
    float v = fmaf(u, 2.0f, lo);                                   // (hi-lo) rounds to 2.0f
    v = fmaxf(v, lo);
    return 1.4142135623730951f * erfinvf(v) * 0.01f;
}

// JAX partitionable threefry (default since jax 0.4.36+):
// element flat index i (< 2^32 here) -> counter (0, i); 32-bit draw = out0 ^ out1
__device__ __forceinline__ float jax_noise_at(unsigned flat_idx)
{
    unsigned o0, o1;
    threefry_0_42(0u, flat_idx, o0, o1);
    return noise_from_bits(o0 ^ o1);
}

// ---------------------------------------------------------------------------
// Kernel A: QKV projections.  out[b][h][t][e] = sum_d X[b,t,d]*W[h,d,e] + bias
// grid: (M/64=64, H=16, 3{Q,K,V}), block 256, 64x64 tile, K-step 32
// ---------------------------------------------------------------------------
__global__ __launch_bounds__(256) void qkv_kernel(
    const float* __restrict__ X,
    const float* __restrict__ Wq, const float* __restrict__ Wk, const float* __restrict__ Wv,
    const float* __restrict__ bq, const float* __restrict__ bk, const float* __restrict__ bv)
{
    __shared__ float Xs[64][33];
    __shared__ float Ws[32][64];

    const int m0 = blockIdx.x * 64;
    const int h  = blockIdx.y;
    const int which = blockIdx.z;

    const float* W; const float* bias; float* out;
    if (which == 0)      { W = Wq; bias = bq; out = g_Q; }
    else if (which == 1) { W = Wk; bias = bk; out = g_K; }
    else                 { W = Wv; bias = bv; out = g_V; }
    W += (size_t)h * ND * DH;

    const int tid = threadIdx.x;
    const int tx = tid & 15;
    const int ty = tid >> 4;

    float c[4][4];
#pragma unroll
    for (int i = 0; i < 4; i++)
#pragma unroll
        for (int j = 0; j < 4; j++) c[i][j] = 0.0f;

    for (int k0 = 0; k0 < ND; k0 += 32) {
        __syncthreads();
        // X tile: 64 rows (n) x 32 cols (d)
#pragma unroll
        for (int f = tid; f < 512; f += 256) {
            int r = f >> 3, c4 = (f & 7) * 4;
            float4 v = *(const float4*)(X + (size_t)(m0 + r) * ND + k0 + c4);
            Xs[r][c4+0] = v.x; Xs[r][c4+1] = v.y; Xs[r][c4+2] = v.z; Xs[r][c4+3] = v.w;
        }
        // W tile: 32 rows (d) x 64 cols (e)
#pragma unroll
        for (int f = tid; f < 512; f += 256) {
            int r = f >> 4, c4 = (f & 15) * 4;
            *(float4*)&Ws[r][c4] = *(const float4*)(W + (size_t)(k0 + r) * DH + c4);
        }
        __syncthreads();
#pragma unroll
        for (int kk = 0; kk < 32; kk++) {
            float a0 = Xs[ty*4+0][kk];
            float a1 = Xs[ty*4+1][kk];
            float a2 = Xs[ty*4+2][kk];
            float a3 = Xs[ty*4+3][kk];
            float4 b4 = *(float4*)&Ws[kk][tx*4];
            c[0][0] = fmaf(a0, b4.x, c[0][0]); c[0][1] = fmaf(a0, b4.y, c[0][1]);
            c[0][2] = fmaf(a0, b4.z, c[0][2]); c[0][3] = fmaf(a0, b4.w, c[0][3]);
            c[1][0] = fmaf(a1, b4.x, c[1][0]); c[1][1] = fmaf(a1, b4.y, c[1][1]);
            c[1][2] = fmaf(a1, b4.z, c[1][2]); c[1][3] = fmaf(a1, b4.w, c[1][3]);
            c[2][0] = fmaf(a2, b4.x, c[2][0]); c[2][1] = fmaf(a2, b4.y, c[2][1]);
            c[2][2] = fmaf(a2, b4.z, c[2][2]); c[2][3] = fmaf(a2, b4.w, c[2][3]);
            c[3][0] = fmaf(a3, b4.x, c[3][0]); c[3][1] = fmaf(a3, b4.y, c[3][1]);
            c[3][2] = fmaf(a3, b4.z, c[3][2]); c[3][3] = fmaf(a3, b4.w, c[3][3]);
        }
    }

#pragma unroll
    for (int i = 0; i < 4; i++) {
        int n = m0 + ty*4 + i;
        int b = n >> 11;
        int t = n & (NT - 1);
        float4 r;
        r.x = c[i][0] + bias[h*DH + tx*4 + 0];
        r.y = c[i][1] + bias[h*DH + tx*4 + 1];
        r.z = c[i][2] + bias[h*DH + tx*4 + 2];
        r.w = c[i][3] + bias[h*DH + tx*4 + 3];
        *(float4*)(out + (((size_t)(b*NH + h))*NT + t)*DH + tx*4) = r;
    }
}

// ---------------------------------------------------------------------------
// Kernel B: causal flash attention with bit-exact JAX noise.
// grid: (T/64=32, H=16), block 128.  Thread = one (b, q) row.  BLK_K = 32.
// ---------------------------------------------------------------------------
__global__ __launch_bounds__(128) void attn_kernel()
{
    __shared__ float Ks[2][32][DH];
    __shared__ float Vs[2][32][DH];

    const int qt  = blockIdx.x;
    const int h   = blockIdx.y;
    const int tid = threadIdx.x;
    const int b   = tid >> 6;
    const int ql  = tid & 63;
    const int q   = qt * 64 + ql;

    const float* Qrow = g_Q + (((size_t)(b*NH + h))*NT + q)*DH;
    float qr[DH];
#pragma unroll
    for (int d = 0; d < DH; d += 4) {
        float4 v = *(const float4*)(Qrow + d);
        qr[d] = v.x; qr[d+1] = v.y; qr[d+2] = v.z; qr[d+3] = v.w;
    }

    float O[DH];
#pragma unroll
    for (int e = 0; e < DH; e++) O[e] = 0.0f;
    float m = -INFINITY;
    float l = 0.0f;

    // flat index into the (B,H,Tq,Tk) noise tensor:
    // i = b*2^26 + ((h*T + q)*T + k)
    const unsigned ibase = ((unsigned)b << 26)
                         + (unsigned)(h*NT + q) * (unsigned)NT;

    const int nkb = qt * 2 + 2;   // covers k in [0, qt*64+64)
    for (int kb = 0; kb < nkb; kb++) {
        const int k0 = kb * 32;
        __syncthreads();
        // cooperative load of K,V block for both batches: 2 x 32 x 64 fp32 each
#pragma unroll
        for (int f = tid; f < 1024; f += 128) {
            int bb = f >> 9;
            int r  = (f >> 4) & 31;
            int c4 = (f & 15) * 4;
            size_t off = (((size_t)(bb*NH + h))*NT + (k0 + r))*DH + c4;
            *(float4*)&Ks[bb][r][c4] = *(const float4*)(g_K + off);
            *(float4*)&Vs[bb][r][c4] = *(const float4*)(g_V + off);
        }
        __syncthreads();

        if (k0 <= q) {
            float s[32];
            float mb = -INFINITY;
#pragma unroll
            for (int kk = 0; kk < 32; kk++) {
                const int k = k0 + kk;
                float sv = -INFINITY;
                if (k <= q) {
                    float acc = 0.0f;
#pragma unroll
                    for (int d = 0; d < DH; d += 4) {
                        float4 kv = *(const float4*)&Ks[b][kk][d];
                        acc = fmaf(qr[d+0], kv.x, acc);
                        acc = fmaf(qr[d+1], kv.y, acc);
                        acc = fmaf(qr[d+2], kv.z, acc);
                        acc = fmaf(qr[d+3], kv.w, acc);
                    }
                    float noise = jax_noise_at(ibase + (unsigned)k);
                    sv = acc * 0.125f + noise;   // 1/sqrt(64)
                }
                s[kk] = sv;
                mb = fmaxf(mb, sv);
            }
            float mnew = fmaxf(m, mb);
            float corr = __expf(m - mnew);        // 0 on first block (m=-inf)
            float psum = 0.0f;
#pragma unroll
            for (int kk = 0; kk < 32; kk++) {
                float p = __expf(s[kk] - mnew);   // masked -> exp(-inf)=0
                s[kk] = p;
                psum += p;
            }
            l = l * corr + psum;
#pragma unroll
            for (int e = 0; e < DH; e++) O[e] *= corr;
#pragma unroll
            for (int kk = 0; kk < 32; kk++) {
                float p = s[kk];
#pragma unroll
                for (int e = 0; e < DH; e += 4) {
                    float4 v = *(const float4*)&Vs[b][kk][e];
                    O[e+0] = fmaf(p, v.x, O[e+0]);
                    O[e+1] = fmaf(p, v.y, O[e+1]);
                    O[e+2] = fmaf(p, v.z, O[e+2]);
                    O[e+3] = fmaf(p, v.w, O[e+3]);
                }
            }
            m = mnew;
        }
    }

    const float inv = 1.0f / l;
    float* Zrow = g_Z + (((size_t)(b*NH + h))*NT + q)*DH;
#pragma unroll
    for (int e = 0; e < DH; e += 4) {
        float4 v;
        v.x = O[e+0] * inv; v.y = O[e+1] * inv;
        v.z = O[e+2] * inv; v.w = O[e+3] * inv;
        *(float4*)(Zrow + e) = v;
    }
}

// ---------------------------------------------------------------------------
// Kernel C: output projection.  out[n][dout] = sum_{h,e} Z[b,h,t,e]*Wo[h,e,dout] + bo
// grid: (64, 16), block 256, 64x64 tile, K-step 32 (one h per 2 K-steps)
// ---------------------------------------------------------------------------
__global__ __launch_bounds__(256) void oproj_kernel(
    const float* __restrict__ Wo, const float* __restrict__ bo,
    float* __restrict__ out)
{
    __shared__ float Zs[64][33];
    __shared__ float Ws[32][64];

    const int m0 = blockIdx.x * 64;
    const int n0 = blockIdx.y * 64;
    const int tid = threadIdx.x;
    const int tx = tid & 15;
    const int ty = tid >> 4;

    float c[4][4];
#pragma unroll
    for (int i = 0; i < 4; i++)
#pragma unroll
        for (int j = 0; j < 4; j++) c[i][j] = 0.0f;

    for (int k0 = 0; k0 < NH*DH; k0 += 32) {
        const int hh = k0 >> 6;
        const int e0 = k0 & 63;
        __syncthreads();
        // Z tile: 64 rows (n) x 32 cols (kdim = h*64+e)
#pragma unroll
        for (int f = tid; f < 512; f += 256) {
            int r = f >> 3, c4 = (f & 7) * 4;
            int n = m0 + r;
            int bb = n >> 11;
            int t  = n & (NT - 1);
            float4 v = *(const float4*)(g_Z + (((size_t)(bb*NH + hh))*NT + t)*DH + e0 + c4);
            Zs[r][c4+0] = v.x; Zs[r][c4+1] = v.y; Zs[r][c4+2] = v.z; Zs[r][c4+3] = v.w;
        }
        // Wo tile: 32 rows (kdim) x 64 cols (dout)
#pragma unroll
        for (int f = tid; f < 512; f += 256) {
            int r = f >> 4, c4 = (f & 15) * 4;
            *(float4*)&Ws[r][c4] = *(const float4*)(Wo + (size_t)(k0 + r)*ND + n0 + c4);
        }
        __syncthreads();
#pragma unroll
        for (int kk = 0; kk < 32; kk++) {
            float a0 = Zs[ty*4+0][kk];
            float a1 = Zs[ty*4+1][kk];
            float a2 = Zs[ty*4+2][kk];
            float a3 = Zs[ty*4+3][kk];
            float4 b4 = *(float4*)&Ws[kk][tx*4];
            c[0][0] = fmaf(a0, b4.x, c[0][0]); c[0][1] = fmaf(a0, b4.y, c[0][1]);
            c[0][2] = fmaf(a0, b4.z, c[0][2]); c[0][3] = fmaf(a0, b4.w, c[0][3]);
            c[1][0] = fmaf(a1, b4.x, c[1][0]); c[1][1] = fmaf(a1, b4.y, c[1][1]);
            c[1][2] = fmaf(a1, b4.z, c[1][2]); c[1][3] = fmaf(a1, b4.w, c[1][3]);
            c[2][0] = fmaf(a2, b4.x, c[2][0]); c[2][1] = fmaf(a2, b4.y, c[2][1]);
            c[2][2] = fmaf(a2, b4.z, c[2][2]); c[2][3] = fmaf(a2, b4.w, c[2][3]);
            c[3][0] = fmaf(a3, b4.x, c[3][0]); c[3][1] = fmaf(a3, b4.y, c[3][1]);
            c[3][2] = fmaf(a3, b4.z, c[3][2]); c[3][3] = fmaf(a3, b4.w, c[3][3]);
        }
    }

#pragma unroll
    for (int i = 0; i < 4; i++) {
        int n = m0 + ty*4 + i;
        float4 r;
        r.x = c[i][0] + bo[n0 + tx*4 + 0];
        r.y = c[i][1] + bo[n0 + tx*4 + 1];
        r.z = c[i][2] + bo[n0 + tx*4 + 2];
        r.w = c[i][3] + bo[n0 + tx*4 + 3];
        *(float4*)(out + (size_t)n*ND + n0 + tx*4) = r;
    }
}

// ---------------------------------------------------------------------------
extern "C" void kernel_launch(void* const* d_in, const int* in_sizes, int n_in,
                              void* d_out, int out_size)
{
    (void)in_sizes; (void)n_in; (void)out_size;
    const float* X  = (const float*)d_in[0];
    const float* Wq = (const float*)d_in[1];
    const float* Wk = (const float*)d_in[2];
    const float* Wv = (const float*)d_in[3];
    const float* Wo = (const float*)d_in[4];
    const float* bq = (const float*)d_in[5];
    const float* bk = (const float*)d_in[6];
    const float* bv = (const float*)d_in[7];
    const float* bo = (const float*)d_in[8];
    float* out = (float*)d_out;

    qkv_kernel<<<dim3(64, 16, 3), 256>>>(X, Wq, Wk, Wv, bq, bk, bv);
    attn_kernel<<<dim3(32, 16), 128>>>();
    oproj_kernel<<<dim3(64, 16), 256>>>(Wo, bo, out);
}

// round 5
// speedup vs baseline: 2.1916x; 2.1916x over previous
#include <cuda_runtime.h>
#include <cstdint>
#include <math.h>

#define NB 2
#define NH 16
#define NT 2048
#define ND 1024
#define DH 64

// Scratch (allocation-free): Q,K,V,Z in [B][H][T][Dh] layout, fp32. 16 MB each.
__device__ float g_Q[NB*NH*NT*DH];
__device__ float g_K[NB*NH*NT*DH];
__device__ float g_V[NB*NH*NT*DH];
__device__ float g_Z[NB*NH*NT*DH];

// ---------------------------------------------------------------------------
// JAX threefry2x32 with key (0, 42)
// ---------------------------------------------------------------------------
__device__ __forceinline__ void threefry_0_42(unsigned x0, unsigned x1,
                                              unsigned &o0, unsigned &o1)
{
    const unsigned ks0 = 0u;
    const unsigned ks1 = 42u;
    const unsigned ks2 = 0x1BD11BDAu ^ 42u;
    x0 += ks0; x1 += ks1;
#define TF_R(r) do { x0 += x1; x1 = __funnelshift_l(x1, x1, (r)); x1 ^= x0; } while (0)
    TF_R(13); TF_R(15); TF_R(26); TF_R(6);
    x0 += ks1; x1 += ks2 + 1u;
    TF_R(17); TF_R(29); TF_R(16); TF_R(24);
    x0 += ks2; x1 += ks0 + 2u;
    TF_R(13); TF_R(15); TF_R(26); TF_R(6);
    x0 += ks0; x1 += ks1 + 3u;
    TF_R(17); TF_R(29); TF_R(16); TF_R(24);
    x0 += ks1; x1 += ks2 + 4u;
    TF_R(13); TF_R(15); TF_R(26); TF_R(6);
    x0 += ks2; x1 += ks0 + 5u;
#undef TF_R
    o0 = x0; o1 = x1;
}

__device__ __forceinline__ float noise_from_bits(unsigned bits)
{
    float u = __uint_as_float((bits >> 9) | 0x3f800000u) - 1.0f;   // [0,1)
    const float lo = -0.99999994f;                                 // nextafter(-1,0)
    float v = fmaf(u, 2.0f, lo);
    v = fmaxf(v, lo);
    return 1.4142135623730951f * erfinvf(v) * 0.01f;
}

// JAX partitionable threefry: counter (0, flat_idx); draw = out0 ^ out1
__device__ __forceinline__ float jax_noise_at(unsigned flat_idx)
{
    unsigned o0, o1;
    threefry_0_42(0u, flat_idx, o0, o1);
    return noise_from_bits(o0 ^ o1);
}

// ---------------------------------------------------------------------------
// Kernel A: QKV projections. 128x64 tile, 256 threads, 8x4 accum/thread.
// grid: (4096/128=32, H=16, 3{Q,K,V})
// ---------------------------------------------------------------------------
__global__ __launch_bounds__(256) void qkv_kernel(
    const float* __restrict__ X,
    const float* __restrict__ Wq, const float* __restrict__ Wk, const float* __restrict__ Wv,
    const float* __restrict__ bq, const float* __restrict__ bk, const float* __restrict__ bv)
{
    __shared__ float Xs[32][132];   // transposed: [k][m]
    __shared__ float Ws[32][64];

    const int m0 = blockIdx.x * 128;
    const int h  = blockIdx.y;
    const int which = blockIdx.z;

    const float* W; const float* bias; float* out;
    if (which == 0)      { W = Wq; bias = bq; out = g_Q; }
    else if (which == 1) { W = Wk; bias = bk; out = g_K; }
    else                 { W = Wv; bias = bv; out = g_V; }
    W += (size_t)h * ND * DH;

    const int tid = threadIdx.x;
    const int tx = tid & 15;     // n/4
    const int ty = tid >> 4;     // m/8

    float c[8][4];
#pragma unroll
    for (int i = 0; i < 8; i++)
#pragma unroll
        for (int j = 0; j < 4; j++) c[i][j] = 0.0f;

    for (int k0 = 0; k0 < ND; k0 += 32) {
        __syncthreads();
        // X tile: 128 rows x 32 cols, stored transposed. 1024 float4, 4/thread.
#pragma unroll
        for (int i = 0; i < 4; i++) {
            int f = tid + i * 256;
            int r = f >> 3, c4 = (f & 7) * 4;
            float4 v = *(const float4*)(X + (size_t)(m0 + r) * ND + k0 + c4);
            Xs[c4+0][r] = v.x; Xs[c4+1][r] = v.y; Xs[c4+2][r] = v.z; Xs[c4+3][r] = v.w;
        }
        // W tile: 32 x 64. 512 float4, 2/thread.
#pragma unroll
        for (int i = 0; i < 2; i++) {
            int f = tid + i * 256;
            int r = f >> 4, c4 = (f & 15) * 4;
            *(float4*)&Ws[r][c4] = *(const float4*)(W + (size_t)(k0 + r) * DH + c4);
        }
        __syncthreads();
#pragma unroll
        for (int kk = 0; kk < 32; kk++) {
            float4 b4 = *(float4*)&Ws[kk][tx*4];
            float4 a0 = *(float4*)&Xs[kk][ty*8];
            float4 a1 = *(float4*)&Xs[kk][ty*8 + 4];
            float a[8] = {a0.x, a0.y, a0.z, a0.w, a1.x, a1.y, a1.z, a1.w};
#pragma unroll
            for (int i = 0; i < 8; i++) {
                c[i][0] = fmaf(a[i], b4.x, c[i][0]);
                c[i][1] = fmaf(a[i], b4.y, c[i][1]);
                c[i][2] = fmaf(a[i], b4.z, c[i][2]);
                c[i][3] = fmaf(a[i], b4.w, c[i][3]);
            }
        }
    }

#pragma unroll
    for (int i = 0; i < 8; i++) {
        int n = m0 + ty*8 + i;
        int b = n >> 11;
        int t = n & (NT - 1);
        float4 r;
        r.x = c[i][0] + bias[h*DH + tx*4 + 0];
        r.y = c[i][1] + bias[h*DH + tx*4 + 1];
        r.z = c[i][2] + bias[h*DH + tx*4 + 2];
        r.w = c[i][3] + bias[h*DH + tx*4 + 3];
        *(float4*)(out + (((size_t)(b*NH + h))*NT + t)*DH + tx*4) = r;
    }
}

// ---------------------------------------------------------------------------
// Kernel B: causal flash attention, 2 threads per (b,q) row (32 dims each).
// block 128 = 32 q x 2 b x 2 half.  grid (64 qtiles reversed, 16 h). BLK_K=32.
// Smem layout [kk][half][b][36] -> the 4 (half,b) combos land on disjoint
// bank groups (offsets 0/4/8/12 mod 32).
// ---------------------------------------------------------------------------
#define KSTR 144   // 2*2*36 floats per kk row

__global__ __launch_bounds__(128, 3) void attn_kernel()
{
    __shared__ float Ks[32 * KSTR];
    __shared__ float Vs[32 * KSTR];

    const int qt   = 63 - blockIdx.x;        // heavy tiles first
    const int h    = blockIdx.y;
    const int tid  = threadIdx.x;
    const int half = tid & 1;
    const int b    = (tid >> 1) & 1;
    const int qi   = tid >> 2;
    const int q    = qt * 32 + qi;
    const int wid  = tid >> 5;
    const int q_warp_max = qt * 32 + wid * 8 + 7;

    // this thread's 32-dim half of the Q row
    float qr[32];
    {
        const float* Qrow = g_Q + (((size_t)(b*NH + h))*NT + q)*DH + half*32;
#pragma unroll
        for (int d = 0; d < 32; d += 4) {
            float4 v = *(const float4*)(Qrow + d);
            qr[d] = v.x; qr[d+1] = v.y; qr[d+2] = v.z; qr[d+3] = v.w;
        }
    }

    float O[32];
#pragma unroll
    for (int e = 0; e < 32; e++) O[e] = 0.0f;
    float m = -INFINITY;
    float l = 0.0f;

    const unsigned ibase = ((unsigned)b << 26)
                         + (unsigned)(h*NT + q) * (unsigned)NT;

    const int myoff = (half*2 + b) * 36;
    const int nkb = qt + 1;

    for (int kb = 0; kb < nkb; kb++) {
        const int k0 = kb * 32;
        __syncthreads();
        // load K,V chunk for both batches: 2 x 32 x 64 floats each
#pragma unroll
        for (int i = 0; i < 8; i++) {
            int f = tid + i * 128;           // 0..1023
            int bb = f >> 9;
            int r  = (f >> 4) & 31;
            int w  = (f & 15) * 4;
            size_t off = (((size_t)(bb*NH + h))*NT + (k0 + r))*DH + w;
            int si = r*KSTR + ((w >> 5)*2 + bb)*36 + (w & 31);
            *(float4*)&Ks[si] = *(const float4*)(g_K + off);
            *(float4*)&Vs[si] = *(const float4*)(g_V + off);
        }
        __syncthreads();

        if (k0 <= q_warp_max) {              // warp-uniform guard
            float s[32];
            float mb = -INFINITY;
#pragma unroll
            for (int j = 0; j < 16; j++) {
                const int kA = k0 + 2*j;
                // half-dot for kA and kA+1, 4-way ILP each
                const float* ra = Ks + (2*j)*KSTR + myoff;
                const float* rb = ra + KSTR;
                float a0=0,a1=0,a2=0,a3=0, b0=0,b1=0,b2=0,b3=0;
#pragma unroll
                for (int d = 0; d < 32; d += 4) {
                    float4 ka = *(const float4*)(ra + d);
                    float4 kbv = *(const float4*)(rb + d);
                    a0 = fmaf(qr[d+0], ka.x, a0);
                    a1 = fmaf(qr[d+1], ka.y, a1);
                    a2 = fmaf(qr[d+2], ka.z, a2);
                    a3 = fmaf(qr[d+3], ka.w, a3);
                    b0 = fmaf(qr[d+0], kbv.x, b0);
                    b1 = fmaf(qr[d+1], kbv.y, b1);
                    b2 = fmaf(qr[d+2], kbv.z, b2);
                    b3 = fmaf(qr[d+3], kbv.w, b3);
                }
                float pa = (a0 + a1) + (a2 + a3);
                float pb = (b0 + b1) + (b2 + b3);
                float dotA = pa + __shfl_xor_sync(0xffffffffu, pa, 1);
                float dotB = pb + __shfl_xor_sync(0xffffffffu, pb, 1);
                // noise: this thread evaluates parity == half, partner the other
                float nself = jax_noise_at(ibase + (unsigned)(kA + half));
                float nx = __shfl_xor_sync(0xffffffffu, nself, 1);
                float nE = half ? nx : nself;
                float nO = half ? nself : nx;
                float sA = (kA   <= q) ? fmaf(dotA, 0.125f, nE) : -INFINITY;
                float sB = (kA+1 <= q) ? fmaf(dotB, 0.125f, nO) : -INFINITY;
                s[2*j]   = sA;
                s[2*j+1] = sB;
                mb = fmaxf(mb, fmaxf(sA, sB));
            }
            float mnew = fmaxf(m, mb);
            float corr = __expf(m - mnew);   // 0 on first chunk
            l *= corr;
#pragma unroll
            for (int e = 0; e < 32; e++) O[e] *= corr;
#pragma unroll
            for (int kk = 0; kk < 32; kk++) {
                float p = __expf(s[kk] - mnew);
                l += p;
                const float* vr = Vs + kk*KSTR + myoff;
#pragma unroll
                for (int e = 0; e < 32; e += 4) {
                    float4 v = *(const float4*)(vr + e);
                    O[e+0] = fmaf(p, v.x, O[e+0]);
                    O[e+1] = fmaf(p, v.y, O[e+1]);
                    O[e+2] = fmaf(p, v.z, O[e+2]);
                    O[e+3] = fmaf(p, v.w, O[e+3]);
                }
            }
            m = mnew;
        }
    }

    const float inv = 1.0f / l;
    float* Zrow = g_Z + (((size_t)(b*NH + h))*NT + q)*DH + half*32;
#pragma unroll
    for (int e = 0; e < 32; e += 4) {
        float4 v;
        v.x = O[e+0]*inv; v.y = O[e+1]*inv; v.z = O[e+2]*inv; v.w = O[e+3]*inv;
        *(float4*)(Zrow + e) = v;
    }
}

// ---------------------------------------------------------------------------
// Kernel C: output projection. 128x64 tile, 256 threads, 8x4 accum/thread.
// grid: (32 mtiles, 16 ntiles)
// ---------------------------------------------------------------------------
__global__ __launch_bounds__(256) void oproj_kernel(
    const float* __restrict__ Wo, const float* __restrict__ bo,
    float* __restrict__ out)
{
    __shared__ float Zs[32][132];   // transposed: [k][m]
    __shared__ float Ws[32][64];

    const int m0 = blockIdx.x * 128;
    const int n0 = blockIdx.y * 64;
    const int tid = threadIdx.x;
    const int tx = tid & 15;
    const int ty = tid >> 4;

    float c[8][4];
#pragma unroll
    for (int i = 0; i < 8; i++)
#pragma unroll
        for (int j = 0; j < 4; j++) c[i][j] = 0.0f;

    for (int k0 = 0; k0 < NH*DH; k0 += 32) {
        const int hh = k0 >> 6;
        const int e0 = k0 & 63;
        __syncthreads();
        // Z tile: 128 rows x 32 k-cols, transposed into smem
#pragma unroll
        for (int i = 0; i < 4; i++) {
            int f = tid + i * 256;
            int r = f >> 3, c4 = (f & 7) * 4;
            int n = m0 + r;
            int bb = n >> 11;
            int t  = n & (NT - 1);
            float4 v = *(const float4*)(g_Z + (((size_t)(bb*NH + hh))*NT + t)*DH + e0 + c4);
            Zs[c4+0][r] = v.x; Zs[c4+1][r] = v.y; Zs[c4+2][r] = v.z; Zs[c4+3][r] = v.w;
        }
        // Wo tile: 32 x 64
#pragma unroll
        for (int i = 0; i < 2; i++) {
            int f = tid + i * 256;
            int r = f >> 4, c4 = (f & 15) * 4;
            *(float4*)&Ws[r][c4] = *(const float4*)(Wo + (size_t)(k0 + r)*ND + n0 + c4);
        }
        __syncthreads();
#pragma unroll
        for (int kk = 0; kk < 32; kk++) {
            float4 b4 = *(float4*)&Ws[kk][tx*4];
            float4 a0 = *(float4*)&Zs[kk][ty*8];
            float4 a1 = *(float4*)&Zs[kk][ty*8 + 4];
            float a[8] = {a0.x, a0.y, a0.z, a0.w, a1.x, a1.y, a1.z, a1.w};
#pragma unroll
            for (int i = 0; i < 8; i++) {
                c[i][0] = fmaf(a[i], b4.x, c[i][0]);
                c[i][1] = fmaf(a[i], b4.y, c[i][1]);
                c[i][2] = fmaf(a[i], b4.z, c[i][2]);
                c[i][3] = fmaf(a[i], b4.w, c[i][3]);
            }
        }
    }

#pragma unroll
    for (int i = 0; i < 8; i++) {
        int n = m0 + ty*8 + i;
        float4 r;
        r.x = c[i][0] + bo[n0 + tx*4 + 0];
        r.y = c[i][1] + bo[n0 + tx*4 + 1];
        r.z = c[i][2] + bo[n0 + tx*4 + 2];
        r.w = c[i][3] + bo[n0 + tx*4 + 3];
        *(float4*)(out + (size_t)n*ND + n0 + tx*4) = r;
    }
}

// ---------------------------------------------------------------------------
extern "C" void kernel_launch(void* const* d_in, const int* in_sizes, int n_in,
                              void* d_out, int out_size)
{
    (void)in_sizes; (void)n_in; (void)out_size;
    const float* X  = (const float*)d_in[0];
    const float* Wq = (const float*)d_in[1];
    const float* Wk = (const float*)d_in[2];
    const float* Wv = (const float*)d_in[3];
    const float* Wo = (const float*)d_in[4];
    const float* bq = (const float*)d_in[5];
    const float* bk = (const float*)d_in[6];
    const float* bv = (const float*)d_in[7];
    const float* bo = (const float*)d_in[8];
    float* out = (float*)d_out;

    qkv_kernel<<<dim3(32, 16, 3), 256>>>(X, Wq, Wk, Wv, bq, bk, bv);
    attn_kernel<<<dim3(64, 16), 128>>>();
    oproj_kernel<<<dim3(32, 16), 256>>>(Wo, bo, out);
}

// round 6
// speedup vs baseline: 2.3371x; 1.0664x over previous
#include <cuda_runtime.h>
#include <cstdint>
#include <math.h>

#define NB 2
#define NH 16
#define NT 2048
#define ND 1024
#define DH 64

typedef unsigned long long u64;

// Scratch (allocation-free): Q,K,V,Z in [B][H][T][Dh] layout, fp32. 16 MB each.
__device__ float g_Q[NB*NH*NT*DH];
__device__ float g_K[NB*NH*NT*DH];
__device__ float g_V[NB*NH*NT*DH];
__device__ float g_Z[NB*NH*NT*DH];

// ---------------------------------------------------------------------------
// Packed f32x2 helpers (Blackwell FFMA2 path — ptxas won't emit these from C++)
// ---------------------------------------------------------------------------
__device__ __forceinline__ u64 pack2(float lo, float hi)
{ u64 r; asm("mov.b64 %0, {%1, %2};" : "=l"(r) : "f"(lo), "f"(hi)); return r; }

__device__ __forceinline__ u64 fma2(u64 a, u64 b, u64 c)
{ u64 d; asm("fma.rn.f32x2 %0, %1, %2, %3;" : "=l"(d) : "l"(a), "l"(b), "l"(c)); return d; }

__device__ __forceinline__ u64 mul2(u64 a, u64 b)
{ u64 d; asm("mul.rn.f32x2 %0, %1, %2;" : "=l"(d) : "l"(a), "l"(b)); return d; }

__device__ __forceinline__ u64 add2(u64 a, u64 b)
{ u64 d; asm("add.rn.f32x2 %0, %1, %2;" : "=l"(d) : "l"(a), "l"(b)); return d; }

__device__ __forceinline__ void unpack2(u64 v, float& lo, float& hi)
{ asm("mov.b64 {%0, %1}, %2;" : "=f"(lo), "=f"(hi) : "l"(v)); }

// ---------------------------------------------------------------------------
// JAX threefry2x32 with key (0, 42)
// ---------------------------------------------------------------------------
__device__ __forceinline__ void threefry_0_42(unsigned x0, unsigned x1,
                                              unsigned &o0, unsigned &o1)
{
    const unsigned ks0 = 0u;
    const unsigned ks1 = 42u;
    const unsigned ks2 = 0x1BD11BDAu ^ 42u;
    x0 += ks0; x1 += ks1;
#define TF_R(r) do { x0 += x1; x1 = __funnelshift_l(x1, x1, (r)); x1 ^= x0; } while (0)
    TF_R(13); TF_R(15); TF_R(26); TF_R(6);
    x0 += ks1; x1 += ks2 + 1u;
    TF_R(17); TF_R(29); TF_R(16); TF_R(24);
    x0 += ks2; x1 += ks0 + 2u;
    TF_R(13); TF_R(15); TF_R(26); TF_R(6);
    x0 += ks0; x1 += ks1 + 3u;
    TF_R(17); TF_R(29); TF_R(16); TF_R(24);
    x0 += ks1; x1 += ks2 + 4u;
    TF_R(13); TF_R(15); TF_R(26); TF_R(6);
    x0 += ks2; x1 += ks0 + 5u;
#undef TF_R
    o0 = x0; o1 = x1;
}

__device__ __forceinline__ float noise_from_bits(unsigned bits)
{
    float u = __uint_as_float((bits >> 9) | 0x3f800000u) - 1.0f;   // [0,1)
    const float lo = -0.99999994f;                                 // nextafter(-1,0)
    float v = fmaf(u, 2.0f, lo);
    v = fmaxf(v, lo);
    return 1.4142135623730951f * erfinvf(v) * 0.01f;
}

// JAX partitionable threefry: counter (0, flat_idx); draw = out0 ^ out1
__device__ __forceinline__ float jax_noise_at(unsigned flat_idx)
{
    unsigned o0, o1;
    threefry_0_42(0u, flat_idx, o0, o1);
    return noise_from_bits(o0 ^ o1);
}

// ---------------------------------------------------------------------------
// Kernel A: QKV projections. 128x64 tile, 256 threads, 8x4 accum (packed m-pairs).
// grid: (32, H=16, 3{Q,K,V})
// ---------------------------------------------------------------------------
__global__ __launch_bounds__(256) void qkv_kernel(
    const float* __restrict__ X,
    const float* __restrict__ Wq, const float* __restrict__ Wk, const float* __restrict__ Wv,
    const float* __restrict__ bq, const float* __restrict__ bk, const float* __restrict__ bv)
{
    __shared__ float Xs[32][132];   // transposed: [k][m]
    __shared__ float Ws[32][64];

    const int m0 = blockIdx.x * 128;
    const int h  = blockIdx.y;
    const int which = blockIdx.z;

    const float* W; const float* bias; float* out;
    if (which == 0)      { W = Wq; bias = bq; out = g_Q; }
    else if (which == 1) { W = Wk; bias = bk; out = g_K; }
    else                 { W = Wv; bias = bv; out = g_V; }
    W += (size_t)h * ND * DH;

    const int tid = threadIdx.x;
    const int tx = tid & 15;     // n/4
    const int ty = tid >> 4;     // m/8

    u64 c2[4][4];                 // [m-pair][n] ; each holds (m=2i, m=2i+1)
#pragma unroll
    for (int i = 0; i < 4; i++)
#pragma unroll
        for (int j = 0; j < 4; j++) c2[i][j] = 0ull;

    for (int k0 = 0; k0 < ND; k0 += 32) {
        __syncthreads();
#pragma unroll
        for (int i = 0; i < 4; i++) {
            int f = tid + i * 256;
            int r = f >> 3, c4 = (f & 7) * 4;
            float4 v = *(const float4*)(X + (size_t)(m0 + r) * ND + k0 + c4);
            Xs[c4+0][r] = v.x; Xs[c4+1][r] = v.y; Xs[c4+2][r] = v.z; Xs[c4+3][r] = v.w;
        }
#pragma unroll
        for (int i = 0; i < 2; i++) {
            int f = tid + i * 256;
            int r = f >> 4, c4 = (f & 15) * 4;
            *(float4*)&Ws[r][c4] = *(const float4*)(W + (size_t)(k0 + r) * DH + c4);
        }
        __syncthreads();
#pragma unroll
        for (int kk = 0; kk < 32; kk++) {
            float4 b4 = *(float4*)&Ws[kk][tx*4];
            u64 bx = pack2(b4.x, b4.x);
            u64 by = pack2(b4.y, b4.y);
            u64 bz = pack2(b4.z, b4.z);
            u64 bw = pack2(b4.w, b4.w);
            ulonglong2 aA = *(const ulonglong2*)&Xs[kk][ty*8];
            ulonglong2 aB = *(const ulonglong2*)&Xs[kk][ty*8 + 4];
            u64 ap[4] = {aA.x, aA.y, aB.x, aB.y};
#pragma unroll
            for (int i = 0; i < 4; i++) {
                c2[i][0] = fma2(ap[i], bx, c2[i][0]);
                c2[i][1] = fma2(ap[i], by, c2[i][1]);
                c2[i][2] = fma2(ap[i], bz, c2[i][2]);
                c2[i][3] = fma2(ap[i], bw, c2[i][3]);
            }
        }
    }

#pragma unroll
    for (int i = 0; i < 4; i++) {
        float lo[4], hi[4];
#pragma unroll
        for (int j = 0; j < 4; j++) unpack2(c2[i][j], lo[j], hi[j]);
#pragma unroll
        for (int half = 0; half < 2; half++) {
            int n = m0 + ty*8 + i*2 + half;
            int b = n >> 11;
            int t = n & (NT - 1);
            const float* cv = half ? hi : lo;
            float4 r;
            r.x = cv[0] + bias[h*DH + tx*4 + 0];
            r.y = cv[1] + bias[h*DH + tx*4 + 1];
            r.z = cv[2] + bias[h*DH + tx*4 + 2];
            r.w = cv[3] + bias[h*DH + tx*4 + 3];
            *(float4*)(out + (((size_t)(b*NH + h))*NT + t)*DH + tx*4) = r;
        }
    }
}

// ---------------------------------------------------------------------------
// Kernel B: causal flash attention, 2 threads per (b,q) row, f32x2 inner loops.
// block 128 = 32 q x 2 b x 2 half.  grid (64 qtiles reversed, 16 h). BLK_K=32.
// ---------------------------------------------------------------------------
#define KSTR 144   // 2*2*36 floats per kk row

__global__ __launch_bounds__(128, 3) void attn_kernel()
{
    __shared__ float Ks[32 * KSTR];
    __shared__ float Vs[32 * KSTR];

    const int qt   = 63 - blockIdx.x;        // heavy tiles first
    const int h    = blockIdx.y;
    const int tid  = threadIdx.x;
    const int half = tid & 1;
    const int b    = (tid >> 1) & 1;
    const int qi   = tid >> 2;
    const int q    = qt * 32 + qi;
    const int wid  = tid >> 5;
    const int q_warp_max = qt * 32 + wid * 8 + 7;

    // this thread's 32-dim half of the Q row, as 16 packed f32x2
    u64 q2[16];
    {
        const float* Qrow = g_Q + (((size_t)(b*NH + h))*NT + q)*DH + half*32;
#pragma unroll
        for (int d = 0; d < 16; d += 2) {
            ulonglong2 v = *(const ulonglong2*)(Qrow + 2*d);
            q2[d] = v.x; q2[d+1] = v.y;
        }
    }

    u64 O2[16];
#pragma unroll
    for (int e = 0; e < 16; e++) O2[e] = 0ull;
    float m = -INFINITY;
    float l = 0.0f;

    const unsigned ibase = ((unsigned)b << 26)
                         + (unsigned)(h*NT + q) * (unsigned)NT;

    const int myoff = (half*2 + b) * 36;
    const int nkb = qt + 1;

    for (int kb = 0; kb < nkb; kb++) {
        const int k0 = kb * 32;
        __syncthreads();
#pragma unroll
        for (int i = 0; i < 8; i++) {
            int f = tid + i * 128;           // 0..1023
            int bb = f >> 9;
            int r  = (f >> 4) & 31;
            int w  = (f & 15) * 4;
            size_t off = (((size_t)(bb*NH + h))*NT + (k0 + r))*DH + w;
            int si = r*KSTR + ((w >> 5)*2 + bb)*36 + (w & 31);
            *(float4*)&Ks[si] = *(const float4*)(g_K + off);
            *(float4*)&Vs[si] = *(const float4*)(g_V + off);
        }
        __syncthreads();

        if (k0 <= q_warp_max) {              // warp-uniform guard
            float s[32];
            float mb = -INFINITY;
#pragma unroll
            for (int j = 0; j < 16; j++) {
                const int kA = k0 + 2*j;
                const u64* ra = (const u64*)(Ks + (2*j)*KSTR + myoff);
                const u64* rb = (const u64*)(Ks + (2*j+1)*KSTR + myoff);
                u64 A0=0,A1=0,A2=0,A3=0, B0=0,B1=0,B2=0,B3=0;
#pragma unroll
                for (int d = 0; d < 16; d += 4) {
                    ulonglong2 ka0 = *(const ulonglong2*)(ra + d);
                    ulonglong2 ka1 = *(const ulonglong2*)(ra + d + 2);
                    ulonglong2 kb0 = *(const ulonglong2*)(rb + d);
                    ulonglong2 kb1 = *(const ulonglong2*)(rb + d + 2);
                    A0 = fma2(q2[d+0], ka0.x, A0);
                    A1 = fma2(q2[d+1], ka0.y, A1);
                    A2 = fma2(q2[d+2], ka1.x, A2);
                    A3 = fma2(q2[d+3], ka1.y, A3);
                    B0 = fma2(q2[d+0], kb0.x, B0);
                    B1 = fma2(q2[d+1], kb0.y, B1);
                    B2 = fma2(q2[d+2], kb1.x, B2);
                    B3 = fma2(q2[d+3], kb1.y, B3);
                }
                u64 sa = add2(add2(A0, A1), add2(A2, A3));
                u64 sb = add2(add2(B0, B1), add2(B2, B3));
                float pal, pah, pbl, pbh;
                unpack2(sa, pal, pah);
                unpack2(sb, pbl, pbh);
                float pa = pal + pah;
                float pb = pbl + pbh;
                float dotA = pa + __shfl_xor_sync(0xffffffffu, pa, 1);
                float dotB = pb + __shfl_xor_sync(0xffffffffu, pb, 1);
                float nself = jax_noise_at(ibase + (unsigned)(kA + half));
                float nx = __shfl_xor_sync(0xffffffffu, nself, 1);
                float nE = half ? nx : nself;
                float nO = half ? nself : nx;
                float sA = (kA   <= q) ? fmaf(dotA, 0.125f, nE) : -INFINITY;
                float sB = (kA+1 <= q) ? fmaf(dotB, 0.125f, nO) : -INFINITY;
                s[2*j]   = sA;
                s[2*j+1] = sB;
                mb = fmaxf(mb, fmaxf(sA, sB));
            }
            float mnew = fmaxf(m, mb);
            float corr = __expf(m - mnew);   // 0 on first chunk
            l *= corr;
            u64 cc = pack2(corr, corr);
#pragma unroll
            for (int e = 0; e < 16; e++) O2[e] = mul2(O2[e], cc);
#pragma unroll
            for (int kk = 0; kk < 32; kk++) {
                float p = __expf(s[kk] - mnew);
                l += p;
                u64 pp = pack2(p, p);
                const u64* vr = (const u64*)(Vs + kk*KSTR + myoff);
#pragma unroll
                for (int e = 0; e < 16; e += 2) {
                    ulonglong2 v = *(const ulonglong2*)(vr + e);
                    O2[e+0] = fma2(pp, v.x, O2[e+0]);
                    O2[e+1] = fma2(pp, v.y, O2[e+1]);
                }
            }
            m = mnew;
        }
    }

    const float inv = 1.0f / l;
    u64 iv = pack2(inv, inv);
    float* Zrow = g_Z + (((size_t)(b*NH + h))*NT + q)*DH + half*32;
#pragma unroll
    for (int e = 0; e < 16; e += 2) {
        u64 r0 = mul2(O2[e],   iv);
        u64 r1 = mul2(O2[e+1], iv);
        float4 v;
        unpack2(r0, v.x, v.y);
        unpack2(r1, v.z, v.w);
        *(float4*)(Zrow + 2*e) = v;
    }
}

// ---------------------------------------------------------------------------
// Kernel C: output projection. 128x64 tile, 256 threads, packed m-pairs.
// grid: (32 mtiles, 16 ntiles)
// ---------------------------------------------------------------------------
__global__ __launch_bounds__(256) void oproj_kernel(
    const float* __restrict__ Wo, const float* __restrict__ bo,
    float* __restrict__ out)
{
    __shared__ float Zs[32][132];   // transposed: [k][m]
    __shared__ float Ws[32][64];

    const int m0 = blockIdx.x * 128;
    const int n0 = blockIdx.y * 64;
    const int tid = threadIdx.x;
    const int tx = tid & 15;
    const int ty = tid >> 4;

    u64 c2[4][4];
#pragma unroll
    for (int i = 0; i < 4; i++)
#pragma unroll
        for (int j = 0; j < 4; j++) c2[i][j] = 0ull;

    for (int k0 = 0; k0 < NH*DH; k0 += 32) {
        const int hh = k0 >> 6;
        const int e0 = k0 & 63;
        __syncthreads();
#pragma unroll
        for (int i = 0; i < 4; i++) {
            int f = tid + i * 256;
            int r = f >> 3, c4 = (f & 7) * 4;
            int n = m0 + r;
            int bb = n >> 11;
            int t  = n & (NT - 1);
            float4 v = *(const float4*)(g_Z + (((size_t)(bb*NH + hh))*NT + t)*DH + e0 + c4);
            Zs[c4+0][r] = v.x; Zs[c4+1][r] = v.y; Zs[c4+2][r] = v.z; Zs[c4+3][r] = v.w;
        }
#pragma unroll
        for (int i = 0; i < 2; i++) {
            int f = tid + i * 256;
            int r = f >> 4, c4 = (f & 15) * 4;
            *(float4*)&Ws[r][c4] = *(const float4*)(Wo + (size_t)(k0 + r)*ND + n0 + c4);
        }
        __syncthreads();
#pragma unroll
        for (int kk = 0; kk < 32; kk++) {
            float4 b4 = *(float4*)&Ws[kk][tx*4];
            u64 bx = pack2(b4.x, b4.x);
            u64 by = pack2(b4.y, b4.y);
            u64 bz = pack2(b4.z, b4.z);
            u64 bw = pack2(b4.w, b4.w);
            ulonglong2 aA = *(const ulonglong2*)&Zs[kk][ty*8];
            ulonglong2 aB = *(const ulonglong2*)&Zs[kk][ty*8 + 4];
            u64 ap[4] = {aA.x, aA.y, aB.x, aB.y};
#pragma unroll
            for (int i = 0; i < 4; i++) {
                c2[i][0] = fma2(ap[i], bx, c2[i][0]);
                c2[i][1] = fma2(ap[i], by, c2[i][1]);
                c2[i][2] = fma2(ap[i], bz, c2[i][2]);
                c2[i][3] = fma2(ap[i], bw, c2[i][3]);
            }
        }
    }

#pragma unroll
    for (int i = 0; i < 4; i++) {
        float lo[4], hi[4];
#pragma unroll
        for (int j = 0; j < 4; j++) unpack2(c2[i][j], lo[j], hi[j]);
#pragma unroll
        for (int half = 0; half < 2; half++) {
            int n = m0 + ty*8 + i*2 + half;
            const float* cv = half ? hi : lo;
            float4 r;
            r.x = cv[0] + bo[n0 + tx*4 + 0];
            r.y = cv[1] + bo[n0 + tx*4 + 1];
            r.z = cv[2] + bo[n0 + tx*4 + 2];
            r.w = cv[3] + bo[n0 + tx*4 + 3];
            *(float4*)(out + (size_t)n*ND + n0 + tx*4) = r;
        }
    }
}

// ---------------------------------------------------------------------------
extern "C" void kernel_launch(void* const* d_in, const int* in_sizes, int n_in,
                              void* d_out, int out_size)
{
    (void)in_sizes; (void)n_in; (void)out_size;
    const float* X  = (const float*)d_in[0];
    const float* Wq = (const float*)d_in[1];
    const float* Wk = (const float*)d_in[2];
    const float* Wv = (const float*)d_in[3];
    const float* Wo = (const float*)d_in[4];
    const float* bq = (const float*)d_in[5];
    const float* bk = (const float*)d_in[6];
    const float* bv = (const float*)d_in[7];
    const float* bo = (const float*)d_in[8];
    float* out = (float*)d_out;

    qkv_kernel<<<dim3(32, 16, 3), 256>>>(X, Wq, Wk, Wv, bq, bk, bv);
    attn_kernel<<<dim3(64, 16), 128>>>();
    oproj_kernel<<<dim3(32, 16), 256>>>(Wo, bo, out);
}

// round 7
// speedup vs baseline: 3.2606x; 1.3952x over previous
#include <cuda_runtime.h>
#include <cstdint>
#include <math.h>

#define NB 2
#define NH 16
#define NT 2048
#define ND 1024
#define DH 64
#define PAD 68

typedef unsigned long long u64;

// Scratch (allocation-free): Q,K,V,Z in [B][H][T][Dh] layout, fp32. 16 MB each.
__device__ float g_Q[NB*NH*NT*DH];
__device__ float g_K[NB*NH*NT*DH];
__device__ float g_V[NB*NH*NT*DH];
__device__ float g_Z[NB*NH*NT*DH];

// ---------------------------------------------------------------------------
// Packed f32x2 helpers (Blackwell FFMA2 path — ptxas won't emit these from C++)
// ---------------------------------------------------------------------------
__device__ __forceinline__ u64 pack2(float lo, float hi)
{ u64 r; asm("mov.b64 %0, {%1, %2};" : "=l"(r) : "f"(lo), "f"(hi)); return r; }

__device__ __forceinline__ u64 fma2(u64 a, u64 b, u64 c)
{ u64 d; asm("fma.rn.f32x2 %0, %1, %2, %3;" : "=l"(d) : "l"(a), "l"(b), "l"(c)); return d; }

__device__ __forceinline__ u64 mul2(u64 a, u64 b)
{ u64 d; asm("mul.rn.f32x2 %0, %1, %2;" : "=l"(d) : "l"(a), "l"(b)); return d; }

__device__ __forceinline__ void unpack2(u64 v, float& lo, float& hi)
{ asm("mov.b64 {%0, %1}, %2;" : "=f"(lo), "=f"(hi) : "l"(v)); }

// ---------------------------------------------------------------------------
// JAX threefry2x32 with key (0, 42)
// ---------------------------------------------------------------------------
__device__ __forceinline__ void threefry_0_42(unsigned x0, unsigned x1,
                                              unsigned &o0, unsigned &o1)
{
    const unsigned ks0 = 0u;
    const unsigned ks1 = 42u;
    const unsigned ks2 = 0x1BD11BDAu ^ 42u;
    x0 += ks0; x1 += ks1;
#define TF_R(r) do { x0 += x1; x1 = __funnelshift_l(x1, x1, (r)); x1 ^= x0; } while (0)
    TF_R(13); TF_R(15); TF_R(26); TF_R(6);
    x0 += ks1; x1 += ks2 + 1u;
    TF_R(17); TF_R(29); TF_R(16); TF_R(24);
    x0 += ks2; x1 += ks0 + 2u;
    TF_R(13); TF_R(15); TF_R(26); TF_R(6);
    x0 += ks0; x1 += ks1 + 3u;
    TF_R(17); TF_R(29); TF_R(16); TF_R(24);
    x0 += ks1; x1 += ks2 + 4u;
    TF_R(13); TF_R(15); TF_R(26); TF_R(6);
    x0 += ks2; x1 += ks0 + 5u;
#undef TF_R
    o0 = x0; o1 = x1;
}

__device__ __forceinline__ float noise_from_bits(unsigned bits)
{
    float u = __uint_as_float((bits >> 9) | 0x3f800000u) - 1.0f;   // [0,1)
    const float lo = -0.99999994f;                                 // nextafter(-1,0)
    float v = fmaf(u, 2.0f, lo);
    v = fmaxf(v, lo);
    return 1.4142135623730951f * erfinvf(v) * 0.01f;
}

// JAX partitionable threefry: counter (0, flat_idx); draw = out0 ^ out1
// __noinline__: called rarely (gated) — keep one copy off the hot I$ path.
__device__ __noinline__ float jax_noise_at(unsigned flat_idx)
{
    unsigned o0, o1;
    threefry_0_42(0u, flat_idx, o0, o1);
    return noise_from_bits(o0 ^ o1);
}

// ---------------------------------------------------------------------------
// Kernel A: QKV projections. 128x64 tile, 256 threads, packed m-pairs.
// grid: (32, H=16, 3{Q,K,V})   [unchanged from R5 — passing]
// ---------------------------------------------------------------------------
__global__ __launch_bounds__(256) void qkv_kernel(
    const float* __restrict__ X,
    const float* __restrict__ Wq, const float* __restrict__ Wk, const float* __restrict__ Wv,
    const float* __restrict__ bq, const float* __restrict__ bk, const float* __restrict__ bv)
{
    __shared__ float Xs[32][132];   // transposed: [k][m]
    __shared__ float Ws[32][64];

    const int m0 = blockIdx.x * 128;
    const int h  = blockIdx.y;
    const int which = blockIdx.z;

    const float* W; const float* bias; float* out;
    if (which == 0)      { W = Wq; bias = bq; out = g_Q; }
    else if (which == 1) { W = Wk; bias = bk; out = g_K; }
    else                 { W = Wv; bias = bv; out = g_V; }
    W += (size_t)h * ND * DH;

    const int tid = threadIdx.x;
    const int tx = tid & 15;
    const int ty = tid >> 4;

    u64 c2[4][4];
#pragma unroll
    for (int i = 0; i < 4; i++)
#pragma unroll
        for (int j = 0; j < 4; j++) c2[i][j] = 0ull;

    for (int k0 = 0; k0 < ND; k0 += 32) {
        __syncthreads();
#pragma unroll
        for (int i = 0; i < 4; i++) {
            int f = tid + i * 256;
            int r = f >> 3, c4 = (f & 7) * 4;
            float4 v = *(const float4*)(X + (size_t)(m0 + r) * ND + k0 + c4);
            Xs[c4+0][r] = v.x; Xs[c4+1][r] = v.y; Xs[c4+2][r] = v.z; Xs[c4+3][r] = v.w;
        }
#pragma unroll
        for (int i = 0; i < 2; i++) {
            int f = tid + i * 256;
            int r = f >> 4, c4 = (f & 15) * 4;
            *(float4*)&Ws[r][c4] = *(const float4*)(W + (size_t)(k0 + r) * DH + c4);
        }
        __syncthreads();
#pragma unroll
        for (int kk = 0; kk < 32; kk++) {
            float4 b4 = *(float4*)&Ws[kk][tx*4];
            u64 bx = pack2(b4.x, b4.x);
            u64 by = pack2(b4.y, b4.y);
            u64 bz = pack2(b4.z, b4.z);
            u64 bw = pack2(b4.w, b4.w);
            ulonglong2 aA = *(const ulonglong2*)&Xs[kk][ty*8];
            ulonglong2 aB = *(const ulonglong2*)&Xs[kk][ty*8 + 4];
            u64 ap[4] = {aA.x, aA.y, aB.x, aB.y};
#pragma unroll
            for (int i = 0; i < 4; i++) {
                c2[i][0] = fma2(ap[i], bx, c2[i][0]);
                c2[i][1] = fma2(ap[i], by, c2[i][1]);
                c2[i][2] = fma2(ap[i], bz, c2[i][2]);
                c2[i][3] = fma2(ap[i], bw, c2[i][3]);
            }
        }
    }

#pragma unroll
    for (int i = 0; i < 4; i++) {
        float lo[4], hi[4];
#pragma unroll
        for (int j = 0; j < 4; j++) unpack2(c2[i][j], lo[j], hi[j]);
#pragma unroll
        for (int half = 0; half < 2; half++) {
            int n = m0 + ty*8 + i*2 + half;
            int b = n >> 11;
            int t = n & (NT - 1);
            const float* cv = half ? hi : lo;
            float4 r;
            r.x = cv[0] + bias[h*DH + tx*4 + 0];
            r.y = cv[1] + bias[h*DH + tx*4 + 1];
            r.z = cv[2] + bias[h*DH + tx*4 + 2];
            r.w = cv[3] + bias[h*DH + tx*4 + 3];
            *(float4*)(out + (((size_t)(b*NH + h))*NT + t)*DH + tx*4) = r;
        }
    }
}

// ---------------------------------------------------------------------------
// Kernel B: block-tiled flash attention.
// Block = (b, h, 64-q-tile), 128 threads (tx 0..15 = cols, ty 0..7 = 8 rows).
// Per 64-key chunk: QK GEMM (smem-tiled) -> register softmax (+gated bit-exact
// JAX noise) -> P to smem -> AV GEMM.  f32x2 accumulators on row pairs.
// Dynamic smem: Qs[d][q] | Ks[k][d] | Vs[k][e] | Ps[k][q], 64x68 each.
// ---------------------------------------------------------------------------
#define ATTN_SMEM (4*64*PAD*4)

__global__ __launch_bounds__(128, 3) void attn_kernel()
{
    extern __shared__ float smbuf[];
    float* Qs = smbuf;               // [d][q]
    float* Ks = smbuf + 64*PAD;      // [k][d]
    float* Vs = smbuf + 2*64*PAD;    // [k][e]
    float* Ps = smbuf + 3*64*PAD;    // [k][q]

    const int qt  = 31 - blockIdx.x;     // heavy q-tiles first
    const int h   = blockIdx.y;
    const int b   = blockIdx.z;
    const int tid = threadIdx.x;
    const int tx  = tid & 15;
    const int ty  = tid >> 4;
    const int q0  = qt * 64;
    const size_t bh = ((size_t)(b*NH + h))*NT;

    // Q tile, transposed into Qs[d][q]  (once per block)
#pragma unroll
    for (int i2 = 0; i2 < 8; i2++) {
        int f = tid + i2*128;
        int r = f >> 4, d4 = (f & 15)*4;
        float4 v = *(const float4*)(g_Q + (bh + q0 + r)*DH + d4);
        Qs[(d4+0)*PAD + r] = v.x;
        Qs[(d4+1)*PAD + r] = v.y;
        Qs[(d4+2)*PAD + r] = v.z;
        Qs[(d4+3)*PAD + r] = v.w;
    }

    float m[8], lp[8];
    unsigned rowb[8];
    u64 O2[4][4];
#pragma unroll
    for (int i = 0; i < 8; i++) {
        m[i] = -INFINITY; lp[i] = 0.0f;
        rowb[i] = ((unsigned)b << 26)
                + (unsigned)(h*NT + q0 + ty*8 + i) * (unsigned)NT;
    }
#pragma unroll
    for (int p = 0; p < 4; p++)
#pragma unroll
        for (int j = 0; j < 4; j++) O2[p][j] = 0ull;

    for (int k0 = 0; k0 <= q0; k0 += 64) {
        __syncthreads();   // prev AV done (and Qs visible on first iter)
        // K,V chunk -> smem (natural [k][d] / [k][e] layout, coalesced)
#pragma unroll
        for (int i2 = 0; i2 < 8; i2++) {
            int f = tid + i2*128;
            int r = f >> 4, d4 = (f & 15)*4;
            size_t off = (bh + k0 + r)*DH + d4;
            *(float4*)&Ks[r*PAD + d4] = *(const float4*)(g_K + off);
            *(float4*)&Vs[r*PAD + d4] = *(const float4*)(g_V + off);
        }
        __syncthreads();

        // ---- QK GEMM: S[8 rows x 4 cols] per thread, f32x2 row pairs ----
        u64 c2[4][4];
#pragma unroll
        for (int p = 0; p < 4; p++)
#pragma unroll
            for (int j = 0; j < 4; j++) c2[p][j] = 0ull;

        for (int d0 = 0; d0 < DH; d0 += 4) {
            float bf[4][4];
#pragma unroll
            for (int j = 0; j < 4; j++) {
                float4 t = *(float4*)&Ks[(tx*4+j)*PAD + d0];
                bf[j][0] = t.x; bf[j][1] = t.y; bf[j][2] = t.z; bf[j][3] = t.w;
            }
#pragma unroll
            for (int dd = 0; dd < 4; dd++) {
                ulonglong2 aA = *(ulonglong2*)&Qs[(d0+dd)*PAD + ty*8];
                ulonglong2 aB = *(ulonglong2*)&Qs[(d0+dd)*PAD + ty*8 + 4];
                u64 ap[4] = {aA.x, aA.y, aB.x, aB.y};
#pragma unroll
                for (int j = 0; j < 4; j++) {
                    u64 bb = pack2(bf[j][dd], bf[j][dd]);
                    c2[0][j] = fma2(ap[0], bb, c2[0][j]);
                    c2[1][j] = fma2(ap[1], bb, c2[1][j]);
                    c2[2][j] = fma2(ap[2], bb, c2[2][j]);
                    c2[3][j] = fma2(ap[3], bb, c2[3][j]);
                }
            }
        }

        // ---- scale + causal mask ----
        float s[8][4];
#pragma unroll
        for (int p = 0; p < 4; p++)
#pragma unroll
            for (int j = 0; j < 4; j++)
                unpack2(c2[p][j], s[2*p][j], s[2*p+1][j]);

        const bool diag = (k0 == q0);
#pragma unroll
        for (int i = 0; i < 8; i++)
#pragma unroll
            for (int j = 0; j < 4; j++) {
                float v = s[i][j] * 0.125f;
                if (diag && (k0 + tx*4 + j > q0 + ty*8 + i)) v = -INFINITY;
                s[i][j] = v;
            }

        // ---- gated bit-exact noise: only keys within 20 of running max ----
        // skipped keys have p < 2e-9; their missing noise perturbs the output
        // by < 1e-9 relative. Running max <= final max, so gating is safe.
        {
            unsigned kb = (unsigned)(k0 + tx*4);
#pragma unroll
            for (int i = 0; i < 8; i++) {
                float thr = m[i] - 20.0f;
#pragma unroll
                for (int j = 0; j < 4; j++)
                    if (s[i][j] > thr)
                        s[i][j] += jax_noise_at(rowb[i] + kb + j);
            }
        }

        // ---- online softmax update (per-row state, width-16 shfl) ----
        float corr[8];
#pragma unroll
        for (int i = 0; i < 8; i++) {
            float rm = fmaxf(fmaxf(s[i][0], s[i][1]), fmaxf(s[i][2], s[i][3]));
            rm = fmaxf(rm, __shfl_xor_sync(0xffffffffu, rm, 1, 16));
            rm = fmaxf(rm, __shfl_xor_sync(0xffffffffu, rm, 2, 16));
            rm = fmaxf(rm, __shfl_xor_sync(0xffffffffu, rm, 4, 16));
            rm = fmaxf(rm, __shfl_xor_sync(0xffffffffu, rm, 8, 16));
            float mn = fmaxf(m[i], rm);
            corr[i] = __expf(m[i] - mn);      // 0 on first chunk
            m[i] = mn;
            float ps = 0.0f;
#pragma unroll
            for (int j = 0; j < 4; j++) {
                float pv = __expf(s[i][j] - mn);   // masked -> 0
                s[i][j] = pv;
                ps += pv;
            }
            lp[i] = lp[i] * corr[i] + ps;
        }
#pragma unroll
        for (int p = 0; p < 4; p++) {
            u64 cc = pack2(corr[2*p], corr[2*p+1]);
#pragma unroll
            for (int j = 0; j < 4; j++) O2[p][j] = mul2(O2[p][j], cc);
        }

        // ---- P -> smem [k][q] ----
#pragma unroll
        for (int j = 0; j < 4; j++) {
            *(float4*)&Ps[(tx*4+j)*PAD + ty*8] =
                make_float4(s[0][j], s[1][j], s[2][j], s[3][j]);
            *(float4*)&Ps[(tx*4+j)*PAD + ty*8 + 4] =
                make_float4(s[4][j], s[5][j], s[6][j], s[7][j]);
        }
        __syncthreads();

        // ---- AV GEMM: O[8 rows x 4 dims] += P * V ----
        for (int kk = 0; kk < 64; kk++) {
            float4 bv = *(float4*)&Vs[kk*PAD + tx*4];
            ulonglong2 aA = *(ulonglong2*)&Ps[kk*PAD + ty*8];
            ulonglong2 aB = *(ulonglong2*)&Ps[kk*PAD + ty*8 + 4];
            u64 ap[4] = {aA.x, aA.y, aB.x, aB.y};
            u64 b0 = pack2(bv.x, bv.x);
            u64 b1 = pack2(bv.y, bv.y);
            u64 b2 = pack2(bv.z, bv.z);
            u64 b3 = pack2(bv.w, bv.w);
#pragma unroll
            for (int p = 0; p < 4; p++) {
                O2[p][0] = fma2(ap[p], b0, O2[p][0]);
                O2[p][1] = fma2(ap[p], b1, O2[p][1]);
                O2[p][2] = fma2(ap[p], b2, O2[p][2]);
                O2[p][3] = fma2(ap[p], b3, O2[p][3]);
            }
        }
    }

    // ---- finalize: reduce l across the 16-lane row group, store Z ----
    float inv[8];
#pragma unroll
    for (int i = 0; i < 8; i++) {
        float l = lp[i];
        l += __shfl_xor_sync(0xffffffffu, l, 1, 16);
        l += __shfl_xor_sync(0xffffffffu, l, 2, 16);
        l += __shfl_xor_sync(0xffffffffu, l, 4, 16);
        l += __shfl_xor_sync(0xffffffffu, l, 8, 16);
        inv[i] = 1.0f / l;
    }
#pragma unroll
    for (int p = 0; p < 4; p++) {
        float lo[4], hi[4];
#pragma unroll
        for (int j = 0; j < 4; j++) unpack2(O2[p][j], lo[j], hi[j]);
        int r0 = ty*8 + 2*p;
        float4 v0 = make_float4(lo[0]*inv[2*p], lo[1]*inv[2*p],
                                lo[2]*inv[2*p], lo[3]*inv[2*p]);
        float4 v1 = make_float4(hi[0]*inv[2*p+1], hi[1]*inv[2*p+1],
                                hi[2]*inv[2*p+1], hi[3]*inv[2*p+1]);
        *(float4*)(g_Z + (bh + q0 + r0    )*DH + tx*4) = v0;
        *(float4*)(g_Z + (bh + q0 + r0 + 1)*DH + tx*4) = v1;
    }
}

// ---------------------------------------------------------------------------
// Kernel C: output projection. 128x64 tile, 256 threads, packed m-pairs.
// grid: (32 mtiles, 16 ntiles)   [unchanged from R5 — passing]
// ---------------------------------------------------------------------------
__global__ __launch_bounds__(256) void oproj_kernel(
    const float* __restrict__ Wo, const float* __restrict__ bo,
    float* __restrict__ out)
{
    __shared__ float Zs[32][132];   // transposed: [k][m]
    __shared__ float Ws[32][64];

    const int m0 = blockIdx.x * 128;
    const int n0 = blockIdx.y * 64;
    const int tid = threadIdx.x;
    const int tx = tid & 15;
    const int ty = tid >> 4;

    u64 c2[4][4];
#pragma unroll
    for (int i = 0; i < 4; i++)
#pragma unroll
        for (int j = 0; j < 4; j++) c2[i][j] = 0ull;

    for (int k0 = 0; k0 < NH*DH; k0 += 32) {
        const int hh = k0 >> 6;
        const int e0 = k0 & 63;
        __syncthreads();
#pragma unroll
        for (int i = 0; i < 4; i++) {
            int f = tid + i * 256;
            int r = f >> 3, c4 = (f & 7) * 4;
            int n = m0 + r;
            int bb = n >> 11;
            int t  = n & (NT - 1);
            float4 v = *(const float4*)(g_Z + (((size_t)(bb*NH + hh))*NT + t)*DH + e0 + c4);
            Zs[c4+0][r] = v.x; Zs[c4+1][r] = v.y; Zs[c4+2][r] = v.z; Zs[c4+3][r] = v.w;
        }
#pragma unroll
        for (int i = 0; i < 2; i++) {
            int f = tid + i * 256;
            int r = f >> 4, c4 = (f & 15) * 4;
            *(float4*)&Ws[r][c4] = *(const float4*)(Wo + (size_t)(k0 + r)*ND + n0 + c4);
        }
        __syncthreads();
#pragma unroll
        for (int kk = 0; kk < 32; kk++) {
            float4 b4 = *(float4*)&Ws[kk][tx*4];
            u64 bx = pack2(b4.x, b4.x);
            u64 by = pack2(b4.y, b4.y);
            u64 bz = pack2(b4.z, b4.z);
            u64 bw = pack2(b4.w, b4.w);
            ulonglong2 aA = *(const ulonglong2*)&Zs[kk][ty*8];
            ulonglong2 aB = *(const ulonglong2*)&Zs[kk][ty*8 + 4];
            u64 ap[4] = {aA.x, aA.y, aB.x, aB.y};
#pragma unroll
            for (int i = 0; i < 4; i++) {
                c2[i][0] = fma2(ap[i], bx, c2[i][0]);
                c2[i][1] = fma2(ap[i], by, c2[i][1]);
                c2[i][2] = fma2(ap[i], bz, c2[i][2]);
                c2[i][3] = fma2(ap[i], bw, c2[i][3]);
            }
        }
    }

#pragma unroll
    for (int i = 0; i < 4; i++) {
        float lo[4], hi[4];
#pragma unroll
        for (int j = 0; j < 4; j++) unpack2(c2[i][j], lo[j], hi[j]);
#pragma unroll
        for (int half = 0; half < 2; half++) {
            int n = m0 + ty*8 + i*2 + half;
            const float* cv = half ? hi : lo;
            float4 r;
            r.x = cv[0] + bo[n0 + tx*4 + 0];
            r.y = cv[1] + bo[n0 + tx*4 + 1];
            r.z = cv[2] + bo[n0 + tx*4 + 2];
            r.w = cv[3] + bo[n0 + tx*4 + 3];
            *(float4*)(out + (size_t)n*ND + n0 + tx*4) = r;
        }
    }
}

// ---------------------------------------------------------------------------
extern "C" void kernel_launch(void* const* d_in, const int* in_sizes, int n_in,
                              void* d_out, int out_size)
{
    (void)in_sizes; (void)n_in; (void)out_size;
    const float* X  = (const float*)d_in[0];
    const float* Wq = (const float*)d_in[1];
    const float* Wk = (const float*)d_in[2];
    const float* Wv = (const float*)d_in[3];
    const float* Wo = (const float*)d_in[4];
    const float* bq = (const float*)d_in[5];
    const float* bk = (const float*)d_in[6];
    const float* bv = (const float*)d_in[7];
    const float* bo = (const float*)d_in[8];
    float* out = (float*)d_out;

    cudaFuncSetAttribute(attn_kernel,
                         cudaFuncAttributeMaxDynamicSharedMemorySize, ATTN_SMEM);

    qkv_kernel<<<dim3(32, 16, 3), 256>>>(X, Wq, Wk, Wv, bq, bk, bv);
    attn_kernel<<<dim3(32, 16, 2), 128, ATTN_SMEM>>>();
    oproj_kernel<<<dim3(32, 16), 256>>>(Wo, bo, out);
}